// round 12
// baseline (speedup 1.0000x reference)
#include <cuda_runtime.h>
#include <cstdint>

typedef unsigned long long u64;
typedef unsigned int u32;

// ===================== f32x2 helpers =====================
__device__ __forceinline__ u64 fma2(u64 a, u64 b, u64 c) {
    u64 d; asm("fma.rn.f32x2 %0, %1, %2, %3;" : "=l"(d) : "l"(a), "l"(b), "l"(c)); return d;
}
__device__ __forceinline__ u64 pack2(float lo, float hi) {
    u64 d; asm("mov.b64 %0, {%1, %2};" : "=l"(d) : "f"(lo), "f"(hi)); return d;
}
__device__ __forceinline__ float2 unpack2(u64 v) {
    float2 r; asm("mov.b64 {%0, %1}, %2;" : "=f"(r.x), "=f"(r.y) : "l"(v)); return r;
}

// Scratch: hidden state + pre-split bf16 planes (u32 = packed bf16x2)
__device__ float g_h[8192 * 1024];
__device__ u32 g_xh[8192 * 784 / 2];
__device__ u32 g_xl[8192 * 784 / 2];
__device__ u32 g_wh[1024 * 784 / 2];
__device__ u32 g_wl[1024 * 784 / 2];

// ===================== mma.sync helpers =====================
__device__ __forceinline__ u32 smem_u32(const void* p) {
    u32 a;
    asm("{ .reg .u64 t; cvta.to.shared.u64 t, %1; cvt.u32.u64 %0, t; }" : "=r"(a) : "l"(p));
    return a;
}

#define LDSM4(r, addr) \
    asm volatile("ldmatrix.sync.aligned.m8n8.x4.shared.b16 {%0,%1,%2,%3}, [%4];" \
        : "=r"((r)[0]), "=r"((r)[1]), "=r"((r)[2]), "=r"((r)[3]) : "r"(addr))

#define MMA_BF16(c, a, b) \
    asm volatile("mma.sync.aligned.m16n8k16.row.col.f32.bf16.bf16.f32 " \
        "{%0,%1,%2,%3}, {%4,%5,%6,%7}, {%8,%9}, {%0,%1,%2,%3};" \
        : "+f"((c)[0]), "+f"((c)[1]), "+f"((c)[2]), "+f"((c)[3]) \
        : "r"((a)[0]), "r"((a)[1]), "r"((a)[2]), "r"((a)[3]), \
          "r"((b)[0]), "r"((b)[1]))

// split float pair -> bf16 hi-plane word + lo-plane word (lo16 = first elem)
__device__ __forceinline__ void split2(float x, float y, u32& hi, u32& lo) {
    u32 h;
    asm("cvt.rn.bf16x2.f32 %0, %1, %2;" : "=r"(h) : "f"(y), "f"(x));
    float hx = __uint_as_float(h << 16);
    float hy = __uint_as_float(h & 0xFFFF0000u);
    float lx = x - hx;
    float ly = y - hy;
    u32 l;
    asm("cvt.rn.bf16x2.f32 %0, %1, %2;" : "=r"(l) : "f"(ly), "f"(lx));
    hi = h; lo = l;
}

// ---------------------------------------------------------------------------
// Kernel 0: pre-split fp32 -> bf16 hi/lo planes (float4-vectorized).
// ---------------------------------------------------------------------------
__global__ void __launch_bounds__(256) split_kernel(
    const float4* __restrict__ src, uint2* __restrict__ hi, uint2* __restrict__ lo,
    int n4)
{
    int i = blockIdx.x * blockDim.x + threadIdx.x;
    if (i < n4) {
        float4 v = src[i];
        u32 h0, l0, h1, l1;
        split2(v.x, v.y, h0, l0);
        split2(v.z, v.w, h1, l1);
        hi[i] = make_uint2(h0, h1);
        lo[i] = make_uint2(l0, l1);
    }
}

// smem geometry: BK=16 -> rows of 16 bf16 in 24-ushort (48B) stride.
static constexpr int ROW_US  = 24;
static constexpr int PLANE_B = 128 * ROW_US * 2;    // 6144 B per plane
static constexpr int STAGE_B = 4 * PLANE_B;         // Ah, Al, Bh, Bl = 24576
static constexpr int GEMM_SMEM = 2 * STAGE_B;       // 49152 dynamic

// ---------------------------------------------------------------------------
// Kernel 1: h = x @ W1^T + b1 from PRE-SPLIT bf16 planes. (round-10 proven)
// CTA 128x128, BK=16, 4 warps (2x2), warp tile 64x64, double-buffered,
// 2 CTAs/SM, A-frag LDSM hoisted across the barrier. bm_base = chunk offset.
// ---------------------------------------------------------------------------
__global__ void __launch_bounds__(128, 2) gemm1_mma(const float* __restrict__ bias,
                                                    int bm_base)
{
    extern __shared__ __align__(16) char dsm[];
    const u32 sb = smem_u32(dsm);

    const int tid = threadIdx.x;
    const int wid = tid >> 5, lane = tid & 31;
    const int wm = wid >> 1;
    const int wn = wid & 1;
    const int bm = (bm_base + blockIdx.y) * 128, bn = blockIdx.x * 128;

    const u32* Ahp = g_xh + (size_t)(bm + tid) * 392;
    const u32* Alp = g_xl + (size_t)(bm + tid) * 392;
    const u32* Bhp = g_wh + (size_t)(bn + tid) * 392;
    const u32* Blp = g_wl + (size_t)(bn + tid) * 392;

    uint4 vah[2], val[2], vbh[2], vbl[2];
    auto LOAD = [&](int kt) {
        const int k2 = kt * 8;
#pragma unroll
        for (int j = 0; j < 2; j++) {
            vah[j] = *(const uint4*)(Ahp + k2 + 4 * j);
            val[j] = *(const uint4*)(Alp + k2 + 4 * j);
            vbh[j] = *(const uint4*)(Bhp + k2 + 4 * j);
            vbl[j] = *(const uint4*)(Blp + k2 + 4 * j);
        }
    };
    auto STORE = [&](int s) {
        char* base = dsm + s * STAGE_B + tid * 48;
#pragma unroll
        for (int j = 0; j < 2; j++) {
            *(uint4*)(base + 16 * j)               = vah[j];
            *(uint4*)(base + PLANE_B + 16 * j)     = val[j];
            *(uint4*)(base + 2 * PLANE_B + 16 * j) = vbh[j];
            *(uint4*)(base + 3 * PLANE_B + 16 * j) = vbl[j];
        }
    };

    float c[4][8][4];
#pragma unroll
    for (int mf = 0; mf < 4; mf++)
#pragma unroll
        for (int nf = 0; nf < 8; nf++)
#pragma unroll
            for (int r = 0; r < 4; r++) c[mf][nf][r] = 0.0f;

    const u32 a_lm = (u32)((wm * 64 + (lane & 15)) * 48 + (lane >> 4) * 16);
    const u32 b_lm = (u32)((wn * 64 + ((lane & 16) >> 1) + (lane & 7)) * 48 + ((lane >> 3) & 1) * 16);

    u32 ah[4][4], al[4][4];
    auto LDA = [&](int s) {
        const u32 aoff = sb + s * STAGE_B + a_lm;
#pragma unroll
        for (int mf = 0; mf < 4; mf++) {
            LDSM4(ah[mf], aoff + mf * 768);
            LDSM4(al[mf], aoff + PLANE_B + mf * 768);
        }
    };
    auto COMPB = [&](int s) {
        const u32 boff = sb + s * STAGE_B + 2 * PLANE_B + b_lm;
#pragma unroll
        for (int g = 0; g < 4; g++) {
            u32 th[4], tl[4];
            LDSM4(th, boff + g * 768);
            LDSM4(tl, boff + PLANE_B + g * 768);
            u32 bh0[2] = { th[0], th[1] }, bh1[2] = { th[2], th[3] };
            u32 bl0[2] = { tl[0], tl[1] }, bl1[2] = { tl[2], tl[3] };
#pragma unroll
            for (int mf = 0; mf < 4; mf++) {
                MMA_BF16(c[mf][2 * g],     ah[mf], bh0);
                MMA_BF16(c[mf][2 * g],     ah[mf], bl0);
                MMA_BF16(c[mf][2 * g],     al[mf], bh0);
                MMA_BF16(c[mf][2 * g + 1], ah[mf], bh1);
                MMA_BF16(c[mf][2 * g + 1], ah[mf], bl1);
                MMA_BF16(c[mf][2 * g + 1], al[mf], bh1);
            }
        }
    };

    LOAD(0);
    STORE(0);
    LOAD(1);
    __syncthreads();
    LDA(0);

#pragma unroll 1
    for (int kt = 0; kt < 49; kt++) {
        const int s = kt & 1;
        if (kt < 48) {
            STORE(s ^ 1);
            if (kt < 47) LOAD(kt + 2);
        }
        COMPB(s);
        __syncthreads();
        if (kt < 48) LDA(s ^ 1);
    }

#pragma unroll
    for (int mf = 0; mf < 4; mf++) {
#pragma unroll
        for (int nf = 0; nf < 8; nf++) {
            const int row = bm + wm * 64 + mf * 16 + (lane >> 2);
            const int col = bn + wn * 64 + nf * 8 + (lane & 3) * 2;
            const float b0 = bias[col], b1 = bias[col + 1];
            float2 v0 = make_float2(c[mf][nf][0] + b0, c[mf][nf][1] + b1);
            float2 v1 = make_float2(c[mf][nf][2] + b0, c[mf][nf][3] + b1);
            *(float2*)(g_h + (size_t)row * 1024 + col) = v0;
            *(float2*)(g_h + (size_t)(row + 8) * 1024 + col) = v1;
        }
    }
}

// ---------------------------------------------------------------------------
// Kernel 2 (fused): RK4 Lorenz96 over [0,1] with h=1/16 (16 steps) + head.
// Block = 128 threads = one PAIR of batch rows; thread t owns 8 features.
// pair_base = chunk offset in row pairs. (round-11 proven shape)
// ---------------------------------------------------------------------------
__global__ void __launch_bounds__(128) rk4_head_kernel(
    const float* __restrict__ W2, const float* __restrict__ b2,
    float* __restrict__ out, int pair_base)
{
    const int t = threadIdx.x;
    const int warp = t >> 5;
    const size_t pr = (size_t)(pair_base + blockIdx.x);
    const float* p0 = g_h + pr * 2048 + t * 8;
    const float* p1 = p0 + 1024;

    const float hf = 1.0f / 16.0f;
    const u64 NEG1 = pack2(-1.0f, -1.0f);
    const u64 F2   = pack2(8.0f, 8.0f);
    const u64 H05  = pack2(hf * 0.5f, hf * 0.5f);
    const u64 H1   = pack2(hf, hf);
    const u64 H6   = pack2(hf / 6.0f, hf / 6.0f);
    const u64 H3   = pack2(hf / 3.0f, hf / 3.0f);

    u64 x[8], y[8], xa[8];
#pragma unroll
    for (int j = 0; j < 2; j++) {
        float4 a = ((const float4*)p0)[j];
        float4 b = ((const float4*)p1)[j];
        x[4 * j + 0] = pack2(a.x, b.x);
        x[4 * j + 1] = pack2(a.y, b.y);
        x[4 * j + 2] = pack2(a.z, b.z);
        x[4 * j + 3] = pack2(a.w, b.w);
    }

    __shared__ u64 sA[2][128], sB[2][128], sC[2][128];
    __shared__ float2 red[4][10];
    __shared__ float2 lg[10];
    __shared__ float lse2[2];

    const int tl = (t + 127) & 127;
    const int tr = (t + 1) & 127;

    sA[0][t] = x[6]; sB[0][t] = x[7]; sC[0][t] = x[0];
    __syncthreads();
    int pb = 0;

#pragma unroll 1
    for (int s = 0; s < 16; s++) {
        {   // stage 1: k1 from x
            u64 ym2 = sA[pb][tl], ym1 = sB[pb][tl], hp1 = sC[pb][tr];
#pragma unroll
            for (int i = 0; i < 8; i++) {
                u64 vc = x[i];
                u64 vp = (i < 7) ? x[i + 1] : hp1;
                u64 k  = fma2(fma2(ym2, NEG1, vp), ym1, fma2(vc, NEG1, F2));
                xa[i]  = fma2(k, H6, x[i]);
                y[i]   = fma2(k, H05, x[i]);
                ym2 = ym1; ym1 = vc;
            }
            pb ^= 1;
            sA[pb][t] = y[6]; sB[pb][t] = y[7]; sC[pb][t] = y[0];
            __syncthreads();
        }
        {   // stage 2: k2 from y
            u64 ym2 = sA[pb][tl], ym1 = sB[pb][tl], hp1 = sC[pb][tr];
#pragma unroll
            for (int i = 0; i < 8; i++) {
                u64 vc = y[i];
                u64 vp = (i < 7) ? y[i + 1] : hp1;
                u64 k  = fma2(fma2(ym2, NEG1, vp), ym1, fma2(vc, NEG1, F2));
                xa[i]  = fma2(k, H3, xa[i]);
                y[i]   = fma2(k, H05, x[i]);
                ym2 = ym1; ym1 = vc;
            }
            pb ^= 1;
            sA[pb][t] = y[6]; sB[pb][t] = y[7]; sC[pb][t] = y[0];
            __syncthreads();
        }
        {   // stage 3: k3 from y
            u64 ym2 = sA[pb][tl], ym1 = sB[pb][tl], hp1 = sC[pb][tr];
#pragma unroll
            for (int i = 0; i < 8; i++) {
                u64 vc = y[i];
                u64 vp = (i < 7) ? y[i + 1] : hp1;
                u64 k  = fma2(fma2(ym2, NEG1, vp), ym1, fma2(vc, NEG1, F2));
                xa[i]  = fma2(k, H3, xa[i]);
                y[i]   = fma2(k, H1, x[i]);
                ym2 = ym1; ym1 = vc;
            }
            pb ^= 1;
            sA[pb][t] = y[6]; sB[pb][t] = y[7]; sC[pb][t] = y[0];
            __syncthreads();
        }
        {   // stage 4: k4 from y; x = xa + h/6 k4
            u64 ym2 = sA[pb][tl], ym1 = sB[pb][tl], hp1 = sC[pb][tr];
#pragma unroll
            for (int i = 0; i < 8; i++) {
                u64 vc = y[i];
                u64 vp = (i < 7) ? y[i + 1] : hp1;
                u64 k  = fma2(fma2(ym2, NEG1, vp), ym1, fma2(vc, NEG1, F2));
                x[i]   = fma2(k, H6, xa[i]);
                ym2 = ym1; ym1 = vc;
            }
            pb ^= 1;
            sA[pb][t] = x[6]; sB[pb][t] = x[7]; sC[pb][t] = x[0];
            __syncthreads();
        }
    }

    // ---- fused head: logits + log_softmax ----
    float lx[10], ly[10];
#pragma unroll
    for (int o = 0; o < 10; o++) {
        const float4* w4 = (const float4*)(W2 + (size_t)o * 1024 + t * 8);
        u64 a = 0ull;
#pragma unroll
        for (int j = 0; j < 2; j++) {
            float4 w = w4[j];
            a = fma2(x[4 * j + 0], pack2(w.x, w.x), a);
            a = fma2(x[4 * j + 1], pack2(w.y, w.y), a);
            a = fma2(x[4 * j + 2], pack2(w.z, w.z), a);
            a = fma2(x[4 * j + 3], pack2(w.w, w.w), a);
        }
        float2 v = unpack2(a);
#pragma unroll
        for (int off = 16; off > 0; off >>= 1) {
            v.x += __shfl_xor_sync(0xFFFFFFFFu, v.x, off);
            v.y += __shfl_xor_sync(0xFFFFFFFFu, v.y, off);
        }
        lx[o] = v.x; ly[o] = v.y;
    }
    if ((t & 31) == 0) {
#pragma unroll
        for (int o = 0; o < 10; o++) red[warp][o] = make_float2(lx[o], ly[o]);
    }
    __syncthreads();
    if (t < 10) {
        float gx = red[0][t].x + red[1][t].x + red[2][t].x + red[3][t].x + b2[t];
        float gy = red[0][t].y + red[1][t].y + red[2][t].y + red[3][t].y + b2[t];
        lg[t] = make_float2(gx, gy);
    }
    __syncthreads();
    if (t < 2) {
        float m = -1e30f;
#pragma unroll
        for (int o = 0; o < 10; o++) {
            float v = (t == 0) ? lg[o].x : lg[o].y;
            m = fmaxf(m, v);
        }
        float sum = 0.0f;
#pragma unroll
        for (int o = 0; o < 10; o++) {
            float v = (t == 0) ? lg[o].x : lg[o].y;
            sum += expf(v - m);
        }
        lse2[t] = logf(sum) + m;
    }
    __syncthreads();
    if (t < 10) {
        out[pr * 20 + t]      = lg[t].x - lse2[0];
        out[pr * 20 + 10 + t] = lg[t].y - lse2[1];
    }
}

// ---------------------------------------------------------------------------
// Launch: chunked fork-join pipeline. gemm chunk c (2048 rows) on the main
// stream; rk4+head for those rows runs on a side stream as soon as the chunk's
// event fires, overlapping the next gemm chunk (different pipes: tensor vs fma).
// Events/stream created fresh each call (host objects only; no device memory).
// ---------------------------------------------------------------------------
extern "C" void kernel_launch(void* const* d_in, const int* in_sizes, int n_in,
                              void* d_out, int out_size)
{
    const float* x  = (const float*)d_in[0];  // [8192, 784]
    const float* W1 = (const float*)d_in[1];  // [1024, 784]
    const float* b1 = (const float*)d_in[2];  // [1024]
    const float* W2 = (const float*)d_in[3];  // [10, 1024]
    const float* b2 = (const float*)d_in[4];  // [10]
    float* out = (float*)d_out;               // [8192, 10]

    cudaFuncSetAttribute(gemm1_mma, cudaFuncAttributeMaxDynamicSharedMemorySize, GEMM_SMEM);

    u32 *xh, *xl, *wh, *wl;
    cudaGetSymbolAddress((void**)&xh, g_xh);
    cudaGetSymbolAddress((void**)&xl, g_xl);
    cudaGetSymbolAddress((void**)&wh, g_wh);
    cudaGetSymbolAddress((void**)&wl, g_wl);

    cudaStream_t s1;
    cudaStreamCreateWithFlags(&s1, cudaStreamNonBlocking);
    cudaEvent_t ev[4], evd;
    for (int i = 0; i < 4; i++) cudaEventCreateWithFlags(&ev[i], cudaEventDisableTiming);
    cudaEventCreateWithFlags(&evd, cudaEventDisableTiming);

    const int nx4 = 8192 * 784 / 4;   // 1,605,632
    const int nw4 = 1024 * 784 / 4;   // 200,704
    split_kernel<<<nw4 / 256, 256>>>((const float4*)W1, (uint2*)wh, (uint2*)wl, nw4);
    split_kernel<<<nx4 / 256, 256>>>((const float4*)x, (uint2*)xh, (uint2*)xl, nx4);

    // 4 chunks of 2048 batch rows each
    for (int c = 0; c < 4; c++) {
        gemm1_mma<<<dim3(8, 16), 128, GEMM_SMEM>>>(b1, c * 16);
        cudaEventRecord(ev[c], 0);
        cudaStreamWaitEvent(s1, ev[c], 0);
        rk4_head_kernel<<<1024, 128, 0, s1>>>(W2, b2, out, c * 1024);
    }
    cudaEventRecord(evd, s1);
    cudaStreamWaitEvent(0, evd, 0);
}

// round 13
// speedup vs baseline: 1.0985x; 1.0985x over previous
#include <cuda_runtime.h>
#include <cstdint>

typedef unsigned long long u64;
typedef unsigned int u32;

// ===================== f32x2 helpers =====================
__device__ __forceinline__ u64 fma2(u64 a, u64 b, u64 c) {
    u64 d; asm("fma.rn.f32x2 %0, %1, %2, %3;" : "=l"(d) : "l"(a), "l"(b), "l"(c)); return d;
}
__device__ __forceinline__ u64 pack2(float lo, float hi) {
    u64 d; asm("mov.b64 %0, {%1, %2};" : "=l"(d) : "f"(lo), "f"(hi)); return d;
}
__device__ __forceinline__ float2 unpack2(u64 v) {
    float2 r; asm("mov.b64 {%0, %1}, %2;" : "=f"(r.x), "=f"(r.y) : "l"(v)); return r;
}

// Scratch: hidden state + pre-split bf16 planes (u32 = packed bf16x2)
__device__ float g_h[8192 * 1024];
__device__ u32 g_xh[8192 * 784 / 2];
__device__ u32 g_xl[8192 * 784 / 2];
__device__ u32 g_wh[1024 * 784 / 2];
__device__ u32 g_wl[1024 * 784 / 2];

// ===================== mma.sync / async-copy helpers =====================
__device__ __forceinline__ u32 smem_u32(const void* p) {
    u32 a;
    asm("{ .reg .u64 t; cvta.to.shared.u64 t, %1; cvt.u32.u64 %0, t; }" : "=r"(a) : "l"(p));
    return a;
}

#define LDSM4(r, addr) \
    asm volatile("ldmatrix.sync.aligned.m8n8.x4.shared.b16 {%0,%1,%2,%3}, [%4];" \
        : "=r"((r)[0]), "=r"((r)[1]), "=r"((r)[2]), "=r"((r)[3]) : "r"(addr))

#define MMA_BF16(c, a, b) \
    asm volatile("mma.sync.aligned.m16n8k16.row.col.f32.bf16.bf16.f32 " \
        "{%0,%1,%2,%3}, {%4,%5,%6,%7}, {%8,%9}, {%0,%1,%2,%3};" \
        : "+f"((c)[0]), "+f"((c)[1]), "+f"((c)[2]), "+f"((c)[3]) \
        : "r"((a)[0]), "r"((a)[1]), "r"((a)[2]), "r"((a)[3]), \
          "r"((b)[0]), "r"((b)[1]))

#define CPASYNC16(dst, src) \
    asm volatile("cp.async.ca.shared.global [%0], [%1], 16;" :: "r"(dst), "l"(src))
#define CPCOMMIT() asm volatile("cp.async.commit_group;" ::: "memory")
#define CPWAIT(n)  asm volatile("cp.async.wait_group %0;" :: "n"(n) : "memory")

// split float pair -> bf16 hi-plane word + lo-plane word (lo16 = first elem)
__device__ __forceinline__ void split2(float x, float y, u32& hi, u32& lo) {
    u32 h;
    asm("cvt.rn.bf16x2.f32 %0, %1, %2;" : "=r"(h) : "f"(y), "f"(x));
    float hx = __uint_as_float(h << 16);
    float hy = __uint_as_float(h & 0xFFFF0000u);
    float lx = x - hx;
    float ly = y - hy;
    u32 l;
    asm("cvt.rn.bf16x2.f32 %0, %1, %2;" : "=r"(l) : "f"(ly), "f"(lx));
    hi = h; lo = l;
}

// ---------------------------------------------------------------------------
// Kernel 0: pre-split fp32 -> bf16 hi/lo planes (float4-vectorized).
// ---------------------------------------------------------------------------
__global__ void __launch_bounds__(256) split_kernel(
    const float4* __restrict__ src, uint2* __restrict__ hi, uint2* __restrict__ lo,
    int n4)
{
    int i = blockIdx.x * blockDim.x + threadIdx.x;
    if (i < n4) {
        float4 v = src[i];
        u32 h0, l0, h1, l1;
        split2(v.x, v.y, h0, l0);
        split2(v.z, v.w, h1, l1);
        hi[i] = make_uint2(h0, h1);
        lo[i] = make_uint2(l0, l1);
    }
}

// smem geometry: BK=16 -> rows of 16 bf16 in 24-ushort (48B) stride.
static constexpr int ROW_US  = 24;
static constexpr int PLANE_B = 128 * ROW_US * 2;    // 6144 B per plane
static constexpr int STAGE_B = 4 * PLANE_B;         // Ah, Al, Bh, Bl = 24576
static constexpr int NSTAGE  = 4;
static constexpr int GEMM_SMEM = NSTAGE * STAGE_B;  // 98304 dynamic

// ---------------------------------------------------------------------------
// Kernel 1: h = x @ W1^T + b1 from PRE-SPLIT bf16 planes.
// CTA 128x128, BK=16 (49 K-tiles), 4 warps (2x2), warp tile 64x64, 2 CTAs/SM.
// 4-stage cp.async ring (LDGSTS): no register staging, 3-tile-deep pipeline.
// A-frag LDSM hoisted across the barrier. One __syncthreads per K-tile.
// ---------------------------------------------------------------------------
__global__ void __launch_bounds__(128, 2) gemm1_mma(const float* __restrict__ bias)
{
    extern __shared__ __align__(16) char dsm[];
    const u32 sb = smem_u32(dsm);

    const int tid = threadIdx.x;
    const int wid = tid >> 5, lane = tid & 31;
    const int wm = wid >> 1;
    const int wn = wid & 1;
    const int bm = blockIdx.y * 128, bn = blockIdx.x * 128;

    const u32* Ahp = g_xh + (size_t)(bm + tid) * 392;
    const u32* Alp = g_xl + (size_t)(bm + tid) * 392;
    const u32* Bhp = g_wh + (size_t)(bn + tid) * 392;
    const u32* Blp = g_wl + (size_t)(bn + tid) * 392;

    // issue tile kt into stage kt&3 (8 x 16B cp.async per thread) + commit
    auto ISSUE = [&](int kt) {
        const u32 dst = sb + (kt & 3) * STAGE_B + tid * 48;
        const int k2 = kt * 8;
        CPASYNC16(dst,                        Ahp + k2);
        CPASYNC16(dst + 16,                   Ahp + k2 + 4);
        CPASYNC16(dst + PLANE_B,              Alp + k2);
        CPASYNC16(dst + PLANE_B + 16,         Alp + k2 + 4);
        CPASYNC16(dst + 2 * PLANE_B,          Bhp + k2);
        CPASYNC16(dst + 2 * PLANE_B + 16,     Bhp + k2 + 4);
        CPASYNC16(dst + 3 * PLANE_B,          Blp + k2);
        CPASYNC16(dst + 3 * PLANE_B + 16,     Blp + k2 + 4);
        CPCOMMIT();
    };

    float c[4][8][4];
#pragma unroll
    for (int mf = 0; mf < 4; mf++)
#pragma unroll
        for (int nf = 0; nf < 8; nf++)
#pragma unroll
            for (int r = 0; r < 4; r++) c[mf][nf][r] = 0.0f;

    const u32 a_lm = (u32)((wm * 64 + (lane & 15)) * 48 + (lane >> 4) * 16);
    const u32 b_lm = (u32)((wn * 64 + ((lane & 16) >> 1) + (lane & 7)) * 48 + ((lane >> 3) & 1) * 16);

    u32 ah[4][4], al[4][4];          // A-frags, live across the barrier
    auto LDA = [&](int s) {
        const u32 aoff = sb + s * STAGE_B + a_lm;
#pragma unroll
        for (int mf = 0; mf < 4; mf++) {
            LDSM4(ah[mf], aoff + mf * 768);
            LDSM4(al[mf], aoff + PLANE_B + mf * 768);
        }
    };
    auto COMPB = [&](int s) {
        const u32 boff = sb + s * STAGE_B + 2 * PLANE_B + b_lm;
#pragma unroll
        for (int g = 0; g < 4; g++) {
            u32 th[4], tl[4];
            LDSM4(th, boff + g * 768);
            LDSM4(tl, boff + PLANE_B + g * 768);
            u32 bh0[2] = { th[0], th[1] }, bh1[2] = { th[2], th[3] };
            u32 bl0[2] = { tl[0], tl[1] }, bl1[2] = { tl[2], tl[3] };
#pragma unroll
            for (int mf = 0; mf < 4; mf++) {
                MMA_BF16(c[mf][2 * g],     ah[mf], bh0);
                MMA_BF16(c[mf][2 * g],     ah[mf], bl0);
                MMA_BF16(c[mf][2 * g],     al[mf], bh0);
                MMA_BF16(c[mf][2 * g + 1], ah[mf], bh1);
                MMA_BF16(c[mf][2 * g + 1], ah[mf], bl1);
                MMA_BF16(c[mf][2 * g + 1], al[mf], bh1);
            }
        }
    };

    // prologue: issue tiles 0..3 (groups 0..3); tile0 ready after wait_group 3
    ISSUE(0); ISSUE(1); ISSUE(2); ISSUE(3);
    CPWAIT(3);
    __syncthreads();
    LDA(0);

    // iter kt: groups issued so far = 4 + kt. wait_group 2 -> tile kt+1 done.
    // Re-issue stage kt&3 with tile kt+4 AFTER the barrier (stage just freed).
#pragma unroll 1
    for (int kt = 0; kt < 49; kt++) {
        const int s = kt & 3;
        COMPB(s);
        if (kt < 48) {
            CPWAIT(2);
            __syncthreads();
            if (kt + 4 <= 48) ISSUE(kt + 4);
            else CPCOMMIT();            // empty group keeps count uniform
            LDA((kt + 1) & 3);
        }
    }

    // epilogue: C + bias -> g_h
#pragma unroll
    for (int mf = 0; mf < 4; mf++) {
#pragma unroll
        for (int nf = 0; nf < 8; nf++) {
            const int row = bm + wm * 64 + mf * 16 + (lane >> 2);
            const int col = bn + wn * 64 + nf * 8 + (lane & 3) * 2;
            const float b0 = bias[col], b1 = bias[col + 1];
            float2 v0 = make_float2(c[mf][nf][0] + b0, c[mf][nf][1] + b1);
            float2 v1 = make_float2(c[mf][nf][2] + b0, c[mf][nf][3] + b1);
            *(float2*)(g_h + (size_t)row * 1024 + col) = v0;
            *(float2*)(g_h + (size_t)(row + 8) * 1024 + col) = v1;
        }
    }
}

// ---------------------------------------------------------------------------
// Kernel 2 (fused): RK4 Lorenz96 over [0,1] with h=1/16 (16 steps) + head.
// Block = 128 threads = one PAIR of batch rows; thread t owns 8 features.
// (round-11 proven shape, serial full-width launch)
// ---------------------------------------------------------------------------
__global__ void __launch_bounds__(128) rk4_head_kernel(
    const float* __restrict__ W2, const float* __restrict__ b2,
    float* __restrict__ out)
{
    const int t = threadIdx.x;
    const int warp = t >> 5;
    const float* p0 = g_h + (size_t)(2 * blockIdx.x) * 1024 + t * 8;
    const float* p1 = p0 + 1024;

    const float hf = 1.0f / 16.0f;
    const u64 NEG1 = pack2(-1.0f, -1.0f);
    const u64 F2   = pack2(8.0f, 8.0f);
    const u64 H05  = pack2(hf * 0.5f, hf * 0.5f);
    const u64 H1   = pack2(hf, hf);
    const u64 H6   = pack2(hf / 6.0f, hf / 6.0f);
    const u64 H3   = pack2(hf / 3.0f, hf / 3.0f);

    u64 x[8], y[8], xa[8];
#pragma unroll
    for (int j = 0; j < 2; j++) {
        float4 a = ((const float4*)p0)[j];
        float4 b = ((const float4*)p1)[j];
        x[4 * j + 0] = pack2(a.x, b.x);
        x[4 * j + 1] = pack2(a.y, b.y);
        x[4 * j + 2] = pack2(a.z, b.z);
        x[4 * j + 3] = pack2(a.w, b.w);
    }

    __shared__ u64 sA[2][128], sB[2][128], sC[2][128];
    __shared__ float2 red[4][10];
    __shared__ float2 lg[10];
    __shared__ float lse2[2];

    const int tl = (t + 127) & 127;
    const int tr = (t + 1) & 127;

    sA[0][t] = x[6]; sB[0][t] = x[7]; sC[0][t] = x[0];
    __syncthreads();
    int pb = 0;

#pragma unroll 1
    for (int s = 0; s < 16; s++) {
        {   // stage 1: k1 from x
            u64 ym2 = sA[pb][tl], ym1 = sB[pb][tl], hp1 = sC[pb][tr];
#pragma unroll
            for (int i = 0; i < 8; i++) {
                u64 vc = x[i];
                u64 vp = (i < 7) ? x[i + 1] : hp1;
                u64 k  = fma2(fma2(ym2, NEG1, vp), ym1, fma2(vc, NEG1, F2));
                xa[i]  = fma2(k, H6, x[i]);
                y[i]   = fma2(k, H05, x[i]);
                ym2 = ym1; ym1 = vc;
            }
            pb ^= 1;
            sA[pb][t] = y[6]; sB[pb][t] = y[7]; sC[pb][t] = y[0];
            __syncthreads();
        }
        {   // stage 2: k2 from y
            u64 ym2 = sA[pb][tl], ym1 = sB[pb][tl], hp1 = sC[pb][tr];
#pragma unroll
            for (int i = 0; i < 8; i++) {
                u64 vc = y[i];
                u64 vp = (i < 7) ? y[i + 1] : hp1;
                u64 k  = fma2(fma2(ym2, NEG1, vp), ym1, fma2(vc, NEG1, F2));
                xa[i]  = fma2(k, H3, xa[i]);
                y[i]   = fma2(k, H05, x[i]);
                ym2 = ym1; ym1 = vc;
            }
            pb ^= 1;
            sA[pb][t] = y[6]; sB[pb][t] = y[7]; sC[pb][t] = y[0];
            __syncthreads();
        }
        {   // stage 3: k3 from y
            u64 ym2 = sA[pb][tl], ym1 = sB[pb][tl], hp1 = sC[pb][tr];
#pragma unroll
            for (int i = 0; i < 8; i++) {
                u64 vc = y[i];
                u64 vp = (i < 7) ? y[i + 1] : hp1;
                u64 k  = fma2(fma2(ym2, NEG1, vp), ym1, fma2(vc, NEG1, F2));
                xa[i]  = fma2(k, H3, xa[i]);
                y[i]   = fma2(k, H1, x[i]);
                ym2 = ym1; ym1 = vc;
            }
            pb ^= 1;
            sA[pb][t] = y[6]; sB[pb][t] = y[7]; sC[pb][t] = y[0];
            __syncthreads();
        }
        {   // stage 4: k4 from y; x = xa + h/6 k4
            u64 ym2 = sA[pb][tl], ym1 = sB[pb][tl], hp1 = sC[pb][tr];
#pragma unroll
            for (int i = 0; i < 8; i++) {
                u64 vc = y[i];
                u64 vp = (i < 7) ? y[i + 1] : hp1;
                u64 k  = fma2(fma2(ym2, NEG1, vp), ym1, fma2(vc, NEG1, F2));
                x[i]   = fma2(k, H6, xa[i]);
                ym2 = ym1; ym1 = vc;
            }
            pb ^= 1;
            sA[pb][t] = x[6]; sB[pb][t] = x[7]; sC[pb][t] = x[0];
            __syncthreads();
        }
    }

    // ---- fused head: logits + log_softmax ----
    float lx[10], ly[10];
#pragma unroll
    for (int o = 0; o < 10; o++) {
        const float4* w4 = (const float4*)(W2 + (size_t)o * 1024 + t * 8);
        u64 a = 0ull;
#pragma unroll
        for (int j = 0; j < 2; j++) {
            float4 w = w4[j];
            a = fma2(x[4 * j + 0], pack2(w.x, w.x), a);
            a = fma2(x[4 * j + 1], pack2(w.y, w.y), a);
            a = fma2(x[4 * j + 2], pack2(w.z, w.z), a);
            a = fma2(x[4 * j + 3], pack2(w.w, w.w), a);
        }
        float2 v = unpack2(a);
#pragma unroll
        for (int off = 16; off > 0; off >>= 1) {
            v.x += __shfl_xor_sync(0xFFFFFFFFu, v.x, off);
            v.y += __shfl_xor_sync(0xFFFFFFFFu, v.y, off);
        }
        lx[o] = v.x; ly[o] = v.y;
    }
    if ((t & 31) == 0) {
#pragma unroll
        for (int o = 0; o < 10; o++) red[warp][o] = make_float2(lx[o], ly[o]);
    }
    __syncthreads();
    if (t < 10) {
        float gx = red[0][t].x + red[1][t].x + red[2][t].x + red[3][t].x + b2[t];
        float gy = red[0][t].y + red[1][t].y + red[2][t].y + red[3][t].y + b2[t];
        lg[t] = make_float2(gx, gy);
    }
    __syncthreads();
    if (t < 2) {
        float m = -1e30f;
#pragma unroll
        for (int o = 0; o < 10; o++) {
            float v = (t == 0) ? lg[o].x : lg[o].y;
            m = fmaxf(m, v);
        }
        float sum = 0.0f;
#pragma unroll
        for (int o = 0; o < 10; o++) {
            float v = (t == 0) ? lg[o].x : lg[o].y;
            sum += expf(v - m);
        }
        lse2[t] = logf(sum) + m;
    }
    __syncthreads();
    if (t < 10) {
        out[(size_t)(2 * blockIdx.x) * 10 + t]     = lg[t].x - lse2[0];
        out[(size_t)(2 * blockIdx.x + 1) * 10 + t] = lg[t].y - lse2[1];
    }
}

// ---------------------------------------------------------------------------
// Launch: serial full-width grids (round-11 structure — chunking regressed).
// ---------------------------------------------------------------------------
extern "C" void kernel_launch(void* const* d_in, const int* in_sizes, int n_in,
                              void* d_out, int out_size)
{
    const float* x  = (const float*)d_in[0];  // [8192, 784]
    const float* W1 = (const float*)d_in[1];  // [1024, 784]
    const float* b1 = (const float*)d_in[2];  // [1024]
    const float* W2 = (const float*)d_in[3];  // [10, 1024]
    const float* b2 = (const float*)d_in[4];  // [10]
    float* out = (float*)d_out;               // [8192, 10]

    cudaFuncSetAttribute(gemm1_mma, cudaFuncAttributeMaxDynamicSharedMemorySize, GEMM_SMEM);

    u32 *xh, *xl, *wh, *wl;
    cudaGetSymbolAddress((void**)&xh, g_xh);
    cudaGetSymbolAddress((void**)&xl, g_xl);
    cudaGetSymbolAddress((void**)&wh, g_wh);
    cudaGetSymbolAddress((void**)&wl, g_wl);

    const int nx4 = 8192 * 784 / 4;   // 1,605,632
    const int nw4 = 1024 * 784 / 4;   // 200,704
    split_kernel<<<nw4 / 256, 256>>>((const float4*)W1, (uint2*)wh, (uint2*)wl, nw4);
    split_kernel<<<nx4 / 256, 256>>>((const float4*)x, (uint2*)xh, (uint2*)xl, nx4);

    dim3 g1(1024 / 128, 8192 / 128);          // (8, 64)
    gemm1_mma<<<g1, 128, GEMM_SMEM>>>(b1);
    rk4_head_kernel<<<8192 / 2, 128>>>(W2, b2, out);
}

// round 14
// speedup vs baseline: 1.1335x; 1.0318x over previous
#include <cuda_runtime.h>
#include <cstdint>

typedef unsigned long long u64;
typedef unsigned int u32;

// ===================== f32x2 helpers =====================
__device__ __forceinline__ u64 fma2(u64 a, u64 b, u64 c) {
    u64 d; asm("fma.rn.f32x2 %0, %1, %2, %3;" : "=l"(d) : "l"(a), "l"(b), "l"(c)); return d;
}
__device__ __forceinline__ u64 pack2(float lo, float hi) {
    u64 d; asm("mov.b64 %0, {%1, %2};" : "=l"(d) : "f"(lo), "f"(hi)); return d;
}
__device__ __forceinline__ float2 unpack2(u64 v) {
    float2 r; asm("mov.b64 {%0, %1}, %2;" : "=f"(r.x), "=f"(r.y) : "l"(v)); return r;
}

// Scratch: hidden state + pre-split bf16 planes, zero-padded to 800 cols
// (400 u32 per row) so BK=32 divides evenly: 800 = 25*32.
__device__ float g_h[8192 * 1024];
__device__ u32 g_xh[8192 * 400];
__device__ u32 g_xl[8192 * 400];
__device__ u32 g_wh[1024 * 400];
__device__ u32 g_wl[1024 * 400];

// ===================== mma.sync helpers =====================
__device__ __forceinline__ u32 smem_u32(const void* p) {
    u32 a;
    asm("{ .reg .u64 t; cvta.to.shared.u64 t, %1; cvt.u32.u64 %0, t; }" : "=r"(a) : "l"(p));
    return a;
}

#define LDSM4(r, addr) \
    asm volatile("ldmatrix.sync.aligned.m8n8.x4.shared.b16 {%0,%1,%2,%3}, [%4];" \
        : "=r"((r)[0]), "=r"((r)[1]), "=r"((r)[2]), "=r"((r)[3]) : "r"(addr))

#define MMA_BF16(c, a, b) \
    asm volatile("mma.sync.aligned.m16n8k16.row.col.f32.bf16.bf16.f32 " \
        "{%0,%1,%2,%3}, {%4,%5,%6,%7}, {%8,%9}, {%0,%1,%2,%3};" \
        : "+f"((c)[0]), "+f"((c)[1]), "+f"((c)[2]), "+f"((c)[3]) \
        : "r"((a)[0]), "r"((a)[1]), "r"((a)[2]), "r"((a)[3]), \
          "r"((b)[0]), "r"((b)[1]))

// split float pair -> bf16 hi-plane word + lo-plane word (lo16 = first elem)
__device__ __forceinline__ void split2(float x, float y, u32& hi, u32& lo) {
    u32 h;
    asm("cvt.rn.bf16x2.f32 %0, %1, %2;" : "=r"(h) : "f"(y), "f"(x));
    float hx = __uint_as_float(h << 16);
    float hy = __uint_as_float(h & 0xFFFF0000u);
    float lx = x - hx;
    float ly = y - hy;
    u32 l;
    asm("cvt.rn.bf16x2.f32 %0, %1, %2;" : "=r"(l) : "f"(ly), "f"(lx));
    hi = h; lo = l;
}

// ---------------------------------------------------------------------------
// Kernel 0 (merged): pre-split x AND W1 into zero-padded bf16 hi/lo planes.
// 200 tasks per row: j<196 convert float4 j; j>=196 write zero pad (8 u32).
// ---------------------------------------------------------------------------
__global__ void __launch_bounds__(256) split_all_kernel(
    const float4* __restrict__ x, const float4* __restrict__ w1)
{
    const int i = blockIdx.x * 256 + threadIdx.x;   // 9216*200 tasks exactly
    const int row = i / 200;
    const int j = i % 200;

    u32 *hi, *lo;
    const float4* src;
    int srow;
    if (row < 8192) { hi = g_xh; lo = g_xl; src = x;  srow = row; }
    else            { hi = g_wh; lo = g_wl; src = w1; srow = row - 8192; }

    const size_t dst = (size_t)srow * 400 + j * 2;
    if (j < 196) {
        float4 v = src[(size_t)srow * 196 + j];
        u32 h0, l0, h1, l1;
        split2(v.x, v.y, h0, l0);
        split2(v.z, v.w, h1, l1);
        *(uint2*)(hi + dst) = make_uint2(h0, h1);
        *(uint2*)(lo + dst) = make_uint2(l0, l1);
    } else {
        *(uint2*)(hi + dst) = make_uint2(0u, 0u);
        *(uint2*)(lo + dst) = make_uint2(0u, 0u);
    }
}

// smem geometry: BK=32 -> rows of 32 bf16 in 40-ushort (80B) stride
// (proven conflict-free for these ldmatrix formulas in rounds 5-7).
static constexpr int PLANE_B = 128 * 40 * 2;        // 10240 B per plane
static constexpr int STAGE_B = 4 * PLANE_B;         // Ah, Al, Bh, Bl = 40960
static constexpr int GEMM_SMEM = 2 * STAGE_B;       // 81920 dynamic

// ---------------------------------------------------------------------------
// Kernel 1: h = x @ W1^T + b1 from PRE-SPLIT padded bf16 planes.
// CTA 128x128, BK=32 (25 tiles, 2 K-slices each -> same product order as the
// BK=16 version, so bit-identical results; pad slice adds exact zeros).
// 4 warps (2x2), warp tile 64x64, double-buffered, 2 CTAs/SM,
// ONE barrier per 32-K tile (25 total vs 49), A-frag LDSM hoisted.
// ---------------------------------------------------------------------------
__global__ void __launch_bounds__(128, 2) gemm1_mma(const float* __restrict__ bias)
{
    extern __shared__ __align__(16) char dsm[];
    const u32 sb = smem_u32(dsm);

    const int tid = threadIdx.x;
    const int wid = tid >> 5, lane = tid & 31;
    const int wm = wid >> 1;
    const int wn = wid & 1;
    const int bm = blockIdx.y * 128, bn = blockIdx.x * 128;

    const u32* Ahp = g_xh + (size_t)(bm + tid) * 400;
    const u32* Alp = g_xl + (size_t)(bm + tid) * 400;
    const u32* Bhp = g_wh + (size_t)(bn + tid) * 400;
    const u32* Blp = g_wl + (size_t)(bn + tid) * 400;

    // staged regs: ONE phase (16 cols = 2 uint4 per plane) at a time
    uint4 vah[2], val[2], vbh[2], vbl[2];
    auto LOADP = [&](int kt, int ph) {
        const int k2 = kt * 16 + ph * 8;
#pragma unroll
        for (int j = 0; j < 2; j++) {
            vah[j] = *(const uint4*)(Ahp + k2 + 4 * j);
            val[j] = *(const uint4*)(Alp + k2 + 4 * j);
            vbh[j] = *(const uint4*)(Bhp + k2 + 4 * j);
            vbl[j] = *(const uint4*)(Blp + k2 + 4 * j);
        }
    };
    auto STOREP = [&](int s, int ph) {
        char* base = dsm + s * STAGE_B + tid * 80 + ph * 32;
#pragma unroll
        for (int j = 0; j < 2; j++) {
            *(uint4*)(base + 16 * j)               = vah[j];
            *(uint4*)(base + PLANE_B + 16 * j)     = val[j];
            *(uint4*)(base + 2 * PLANE_B + 16 * j) = vbh[j];
            *(uint4*)(base + 3 * PLANE_B + 16 * j) = vbl[j];
        }
    };

    float c[4][8][4];
#pragma unroll
    for (int mf = 0; mf < 4; mf++)
#pragma unroll
        for (int nf = 0; nf < 8; nf++)
#pragma unroll
            for (int r = 0; r < 4; r++) c[mf][nf][r] = 0.0f;

    // ldmatrix per-lane byte offsets within a plane (80B row stride)
    const u32 a_lm = (u32)((wm * 64 + (lane & 15)) * 80 + (lane >> 4) * 16);
    const u32 b_lm = (u32)((wn * 64 + ((lane & 16) >> 1) + (lane & 7)) * 80 + ((lane >> 3) & 1) * 16);

    u32 ah[4][4], al[4][4];          // A-frags for current slice
    auto LDA = [&](int s, int ks) {
        const u32 aoff = sb + s * STAGE_B + a_lm + ks * 32;
#pragma unroll
        for (int mf = 0; mf < 4; mf++) {
            LDSM4(ah[mf], aoff + mf * 1280);
            LDSM4(al[mf], aoff + PLANE_B + mf * 1280);
        }
    };
    auto COMPB = [&](int s, int ks) {
        const u32 boff = sb + s * STAGE_B + 2 * PLANE_B + b_lm + ks * 32;
#pragma unroll
        for (int g = 0; g < 4; g++) {
            u32 th[4], tl[4];
            LDSM4(th, boff + g * 1280);
            LDSM4(tl, boff + PLANE_B + g * 1280);
            u32 bh0[2] = { th[0], th[1] }, bh1[2] = { th[2], th[3] };
            u32 bl0[2] = { tl[0], tl[1] }, bl1[2] = { tl[2], tl[3] };
#pragma unroll
            for (int mf = 0; mf < 4; mf++) {
                MMA_BF16(c[mf][2 * g],     ah[mf], bh0);
                MMA_BF16(c[mf][2 * g],     ah[mf], bl0);
                MMA_BF16(c[mf][2 * g],     al[mf], bh0);
                MMA_BF16(c[mf][2 * g + 1], ah[mf], bh1);
                MMA_BF16(c[mf][2 * g + 1], ah[mf], bl1);
                MMA_BF16(c[mf][2 * g + 1], al[mf], bh1);
            }
        }
    };

    // prologue: tile0 fully stored; tile1 phase1 staged; A-frags(buf0,slice0)
    LOADP(0, 0); STOREP(0, 0);
    LOADP(0, 1); STOREP(0, 1);
    LOADP(1, 0);
    __syncthreads();
    LDA(0, 0);

#pragma unroll 1
    for (int kt = 0; kt < 25; kt++) {
        const int s = kt & 1;
        if (kt < 24) { STOREP(s ^ 1, 0); LOADP(kt + 1, 1); }   // tile kt+1
        COMPB(s, 0);
        LDA(s, 1);
        if (kt < 24) { STOREP(s ^ 1, 1); if (kt < 23) LOADP(kt + 2, 0); }
        COMPB(s, 1);          // tile 24 slice 1 = zero pad (exact zeros)
        __syncthreads();
        if (kt < 24) LDA(s ^ 1, 0);
    }

    // epilogue: C + bias -> g_h
#pragma unroll
    for (int mf = 0; mf < 4; mf++) {
#pragma unroll
        for (int nf = 0; nf < 8; nf++) {
            const int row = bm + wm * 64 + mf * 16 + (lane >> 2);
            const int col = bn + wn * 64 + nf * 8 + (lane & 3) * 2;
            const float b0 = bias[col], b1 = bias[col + 1];
            float2 v0 = make_float2(c[mf][nf][0] + b0, c[mf][nf][1] + b1);
            float2 v1 = make_float2(c[mf][nf][2] + b0, c[mf][nf][3] + b1);
            *(float2*)(g_h + (size_t)row * 1024 + col) = v0;
            *(float2*)(g_h + (size_t)(row + 8) * 1024 + col) = v1;
        }
    }
}

// ---------------------------------------------------------------------------
// Kernel 2 (fused): RK4 Lorenz96 over [0,1] with h=1/16 (16 steps) + head.
// Block = 128 threads = one PAIR of batch rows; thread t owns 8 features.
// (round-11 proven version, unchanged)
// ---------------------------------------------------------------------------
__global__ void __launch_bounds__(128) rk4_head_kernel(
    const float* __restrict__ W2, const float* __restrict__ b2,
    float* __restrict__ out)
{
    const int t = threadIdx.x;
    const int warp = t >> 5;
    const float* p0 = g_h + (size_t)(2 * blockIdx.x) * 1024 + t * 8;
    const float* p1 = p0 + 1024;

    const float hf = 1.0f / 16.0f;
    const u64 NEG1 = pack2(-1.0f, -1.0f);
    const u64 F2   = pack2(8.0f, 8.0f);
    const u64 H05  = pack2(hf * 0.5f, hf * 0.5f);
    const u64 H1   = pack2(hf, hf);
    const u64 H6   = pack2(hf / 6.0f, hf / 6.0f);
    const u64 H3   = pack2(hf / 3.0f, hf / 3.0f);

    u64 x[8], y[8], xa[8];
#pragma unroll
    for (int j = 0; j < 2; j++) {
        float4 a = ((const float4*)p0)[j];
        float4 b = ((const float4*)p1)[j];
        x[4 * j + 0] = pack2(a.x, b.x);
        x[4 * j + 1] = pack2(a.y, b.y);
        x[4 * j + 2] = pack2(a.z, b.z);
        x[4 * j + 3] = pack2(a.w, b.w);
    }

    __shared__ u64 sA[2][128], sB[2][128], sC[2][128];
    __shared__ float2 red[4][10];
    __shared__ float2 lg[10];
    __shared__ float lse2[2];

    const int tl = (t + 127) & 127;
    const int tr = (t + 1) & 127;

    sA[0][t] = x[6]; sB[0][t] = x[7]; sC[0][t] = x[0];
    __syncthreads();
    int pb = 0;

#pragma unroll 1
    for (int s = 0; s < 16; s++) {
        {   // stage 1: k1 from x
            u64 ym2 = sA[pb][tl], ym1 = sB[pb][tl], hp1 = sC[pb][tr];
#pragma unroll
            for (int i = 0; i < 8; i++) {
                u64 vc = x[i];
                u64 vp = (i < 7) ? x[i + 1] : hp1;
                u64 k  = fma2(fma2(ym2, NEG1, vp), ym1, fma2(vc, NEG1, F2));
                xa[i]  = fma2(k, H6, x[i]);
                y[i]   = fma2(k, H05, x[i]);
                ym2 = ym1; ym1 = vc;
            }
            pb ^= 1;
            sA[pb][t] = y[6]; sB[pb][t] = y[7]; sC[pb][t] = y[0];
            __syncthreads();
        }
        {   // stage 2: k2 from y
            u64 ym2 = sA[pb][tl], ym1 = sB[pb][tl], hp1 = sC[pb][tr];
#pragma unroll
            for (int i = 0; i < 8; i++) {
                u64 vc = y[i];
                u64 vp = (i < 7) ? y[i + 1] : hp1;
                u64 k  = fma2(fma2(ym2, NEG1, vp), ym1, fma2(vc, NEG1, F2));
                xa[i]  = fma2(k, H3, xa[i]);
                y[i]   = fma2(k, H05, x[i]);
                ym2 = ym1; ym1 = vc;
            }
            pb ^= 1;
            sA[pb][t] = y[6]; sB[pb][t] = y[7]; sC[pb][t] = y[0];
            __syncthreads();
        }
        {   // stage 3: k3 from y
            u64 ym2 = sA[pb][tl], ym1 = sB[pb][tl], hp1 = sC[pb][tr];
#pragma unroll
            for (int i = 0; i < 8; i++) {
                u64 vc = y[i];
                u64 vp = (i < 7) ? y[i + 1] : hp1;
                u64 k  = fma2(fma2(ym2, NEG1, vp), ym1, fma2(vc, NEG1, F2));
                xa[i]  = fma2(k, H3, xa[i]);
                y[i]   = fma2(k, H1, x[i]);
                ym2 = ym1; ym1 = vc;
            }
            pb ^= 1;
            sA[pb][t] = y[6]; sB[pb][t] = y[7]; sC[pb][t] = y[0];
            __syncthreads();
        }
        {   // stage 4: k4 from y; x = xa + h/6 k4
            u64 ym2 = sA[pb][tl], ym1 = sB[pb][tl], hp1 = sC[pb][tr];
#pragma unroll
            for (int i = 0; i < 8; i++) {
                u64 vc = y[i];
                u64 vp = (i < 7) ? y[i + 1] : hp1;
                u64 k  = fma2(fma2(ym2, NEG1, vp), ym1, fma2(vc, NEG1, F2));
                x[i]   = fma2(k, H6, xa[i]);
                ym2 = ym1; ym1 = vc;
            }
            pb ^= 1;
            sA[pb][t] = x[6]; sB[pb][t] = x[7]; sC[pb][t] = x[0];
            __syncthreads();
        }
    }

    // ---- fused head: logits + log_softmax ----
    float lx[10], ly[10];
#pragma unroll
    for (int o = 0; o < 10; o++) {
        const float4* w4 = (const float4*)(W2 + (size_t)o * 1024 + t * 8);
        u64 a = 0ull;
#pragma unroll
        for (int j = 0; j < 2; j++) {
            float4 w = w4[j];
            a = fma2(x[4 * j + 0], pack2(w.x, w.x), a);
            a = fma2(x[4 * j + 1], pack2(w.y, w.y), a);
            a = fma2(x[4 * j + 2], pack2(w.z, w.z), a);
            a = fma2(x[4 * j + 3], pack2(w.w, w.w), a);
        }
        float2 v = unpack2(a);
#pragma unroll
        for (int off = 16; off > 0; off >>= 1) {
            v.x += __shfl_xor_sync(0xFFFFFFFFu, v.x, off);
            v.y += __shfl_xor_sync(0xFFFFFFFFu, v.y, off);
        }
        lx[o] = v.x; ly[o] = v.y;
    }
    if ((t & 31) == 0) {
#pragma unroll
        for (int o = 0; o < 10; o++) red[warp][o] = make_float2(lx[o], ly[o]);
    }
    __syncthreads();
    if (t < 10) {
        float gx = red[0][t].x + red[1][t].x + red[2][t].x + red[3][t].x + b2[t];
        float gy = red[0][t].y + red[1][t].y + red[2][t].y + red[3][t].y + b2[t];
        lg[t] = make_float2(gx, gy);
    }
    __syncthreads();
    if (t < 2) {
        float m = -1e30f;
#pragma unroll
        for (int o = 0; o < 10; o++) {
            float v = (t == 0) ? lg[o].x : lg[o].y;
            m = fmaxf(m, v);
        }
        float sum = 0.0f;
#pragma unroll
        for (int o = 0; o < 10; o++) {
            float v = (t == 0) ? lg[o].x : lg[o].y;
            sum += expf(v - m);
        }
        lse2[t] = logf(sum) + m;
    }
    __syncthreads();
    if (t < 10) {
        out[(size_t)(2 * blockIdx.x) * 10 + t]     = lg[t].x - lse2[0];
        out[(size_t)(2 * blockIdx.x + 1) * 10 + t] = lg[t].y - lse2[1];
    }
}

// ---------------------------------------------------------------------------
// Launch: serial full-width grids (chunking/overlap regressed in round 12).
// ---------------------------------------------------------------------------
extern "C" void kernel_launch(void* const* d_in, const int* in_sizes, int n_in,
                              void* d_out, int out_size)
{
    const float* x  = (const float*)d_in[0];  // [8192, 784]
    const float* W1 = (const float*)d_in[1];  // [1024, 784]
    const float* b1 = (const float*)d_in[2];  // [1024]
    const float* W2 = (const float*)d_in[3];  // [10, 1024]
    const float* b2 = (const float*)d_in[4];  // [10]
    float* out = (float*)d_out;               // [8192, 10]

    cudaFuncSetAttribute(gemm1_mma, cudaFuncAttributeMaxDynamicSharedMemorySize, GEMM_SMEM);

    // merged split: (8192 + 1024) rows x 200 tasks = 1,843,200 = 7200 * 256
    split_all_kernel<<<7200, 256>>>((const float4*)x, (const float4*)W1);

    dim3 g1(1024 / 128, 8192 / 128);          // (8, 64)
    gemm1_mma<<<g1, 128, GEMM_SMEM>>>(b1);
    rk4_head_kernel<<<8192 / 2, 128>>>(W2, b2, out);
}

// round 15
// speedup vs baseline: 1.2391x; 1.0932x over previous
#include <cuda_runtime.h>
#include <cstdint>

typedef unsigned long long u64;
typedef unsigned int u32;

// ===================== f32x2 helpers =====================
__device__ __forceinline__ u64 fma2(u64 a, u64 b, u64 c) {
    u64 d; asm("fma.rn.f32x2 %0, %1, %2, %3;" : "=l"(d) : "l"(a), "l"(b), "l"(c)); return d;
}
__device__ __forceinline__ u64 pack2(float lo, float hi) {
    u64 d; asm("mov.b64 %0, {%1, %2};" : "=l"(d) : "f"(lo), "f"(hi)); return d;
}
__device__ __forceinline__ float2 unpack2(u64 v) {
    float2 r; asm("mov.b64 {%0, %1}, %2;" : "=f"(r.x), "=f"(r.y) : "l"(v)); return r;
}

// Scratch: hidden state + pre-split bf16 planes (u32 = packed bf16x2),
// 392 u32 per row (784 fp32), no padding (BK=16 divides 784 exactly).
__device__ float g_h[8192 * 1024];
__device__ u32 g_xh[8192 * 392];
__device__ u32 g_xl[8192 * 392];
__device__ u32 g_wh[1024 * 392];
__device__ u32 g_wl[1024 * 392];

// ===================== mma.sync helpers =====================
__device__ __forceinline__ u32 smem_u32(const void* p) {
    u32 a;
    asm("{ .reg .u64 t; cvta.to.shared.u64 t, %1; cvt.u32.u64 %0, t; }" : "=r"(a) : "l"(p));
    return a;
}

#define LDSM4(r, addr) \
    asm volatile("ldmatrix.sync.aligned.m8n8.x4.shared.b16 {%0,%1,%2,%3}, [%4];" \
        : "=r"((r)[0]), "=r"((r)[1]), "=r"((r)[2]), "=r"((r)[3]) : "r"(addr))

#define MMA_BF16(c, a, b) \
    asm volatile("mma.sync.aligned.m16n8k16.row.col.f32.bf16.bf16.f32 " \
        "{%0,%1,%2,%3}, {%4,%5,%6,%7}, {%8,%9}, {%0,%1,%2,%3};" \
        : "+f"((c)[0]), "+f"((c)[1]), "+f"((c)[2]), "+f"((c)[3]) \
        : "r"((a)[0]), "r"((a)[1]), "r"((a)[2]), "r"((a)[3]), \
          "r"((b)[0]), "r"((b)[1]))

// split float pair -> bf16 hi-plane word + lo-plane word (lo16 = first elem)
__device__ __forceinline__ void split2(float x, float y, u32& hi, u32& lo) {
    u32 h;
    asm("cvt.rn.bf16x2.f32 %0, %1, %2;" : "=r"(h) : "f"(y), "f"(x));
    float hx = __uint_as_float(h << 16);
    float hy = __uint_as_float(h & 0xFFFF0000u);
    float lx = x - hx;
    float ly = y - hy;
    u32 l;
    asm("cvt.rn.bf16x2.f32 %0, %1, %2;" : "=r"(l) : "f"(ly), "f"(lx));
    hi = h; lo = l;
}

// ---------------------------------------------------------------------------
// Kernel 0 (merged): pre-split x AND W1 into bf16 hi/lo planes in one launch.
// 9216 rows x 196 float4 tasks = 1,806,336 = 7056 * 256 exactly.
// ---------------------------------------------------------------------------
__global__ void __launch_bounds__(256) split_all_kernel(
    const float4* __restrict__ x, const float4* __restrict__ w1)
{
    const int i = blockIdx.x * 256 + threadIdx.x;
    const int row = i / 196;
    const int j = i % 196;

    u32 *hi, *lo;
    const float4* src;
    int srow;
    if (row < 8192) { hi = g_xh; lo = g_xl; src = x;  srow = row; }
    else            { hi = g_wh; lo = g_wl; src = w1; srow = row - 8192; }

    float4 v = src[(size_t)srow * 196 + j];
    u32 h0, l0, h1, l1;
    split2(v.x, v.y, h0, l0);
    split2(v.z, v.w, h1, l1);
    const size_t dst = (size_t)srow * 392 + j * 2;
    *(uint2*)(hi + dst) = make_uint2(h0, h1);
    *(uint2*)(lo + dst) = make_uint2(l0, l1);
}

// smem geometry: BK=16 -> rows of 16 bf16 in 24-ushort (48B) stride.
static constexpr int ROW_US  = 24;
static constexpr int PLANE_B = 128 * ROW_US * 2;    // 6144 B per plane
static constexpr int STAGE_B = 4 * PLANE_B;         // Ah, Al, Bh, Bl = 24576
static constexpr int GEMM_SMEM = 2 * STAGE_B;       // 49152 dynamic

// ---------------------------------------------------------------------------
// Kernel 1: h = x @ W1^T + b1 from PRE-SPLIT bf16 planes. (round-11 proven)
// CTA 128x128, BK=16 (784 = 49*16), 4 warps (2x2), warp tile 64x64,
// double-buffered, 2 CTAs/SM, A-frag LDSM hoisted across the barrier.
// ---------------------------------------------------------------------------
__global__ void __launch_bounds__(128, 2) gemm1_mma(const float* __restrict__ bias)
{
    extern __shared__ __align__(16) char dsm[];
    const u32 sb = smem_u32(dsm);

    const int tid = threadIdx.x;
    const int wid = tid >> 5, lane = tid & 31;
    const int wm = wid >> 1;
    const int wn = wid & 1;
    const int bm = blockIdx.y * 128, bn = blockIdx.x * 128;

    const u32* Ahp = g_xh + (size_t)(bm + tid) * 392;
    const u32* Alp = g_xl + (size_t)(bm + tid) * 392;
    const u32* Bhp = g_wh + (size_t)(bn + tid) * 392;
    const u32* Blp = g_wl + (size_t)(bn + tid) * 392;

    uint4 vah[2], val[2], vbh[2], vbl[2];
    auto LOAD = [&](int kt) {
        const int k2 = kt * 8;
#pragma unroll
        for (int j = 0; j < 2; j++) {
            vah[j] = *(const uint4*)(Ahp + k2 + 4 * j);
            val[j] = *(const uint4*)(Alp + k2 + 4 * j);
            vbh[j] = *(const uint4*)(Bhp + k2 + 4 * j);
            vbl[j] = *(const uint4*)(Blp + k2 + 4 * j);
        }
    };
    auto STORE = [&](int s) {
        char* base = dsm + s * STAGE_B + tid * 48;
#pragma unroll
        for (int j = 0; j < 2; j++) {
            *(uint4*)(base + 16 * j)               = vah[j];
            *(uint4*)(base + PLANE_B + 16 * j)     = val[j];
            *(uint4*)(base + 2 * PLANE_B + 16 * j) = vbh[j];
            *(uint4*)(base + 3 * PLANE_B + 16 * j) = vbl[j];
        }
    };

    float c[4][8][4];
#pragma unroll
    for (int mf = 0; mf < 4; mf++)
#pragma unroll
        for (int nf = 0; nf < 8; nf++)
#pragma unroll
            for (int r = 0; r < 4; r++) c[mf][nf][r] = 0.0f;

    const u32 a_lm = (u32)((wm * 64 + (lane & 15)) * 48 + (lane >> 4) * 16);
    const u32 b_lm = (u32)((wn * 64 + ((lane & 16) >> 1) + (lane & 7)) * 48 + ((lane >> 3) & 1) * 16);

    u32 ah[4][4], al[4][4];          // A-frags, live across the barrier
    auto LDA = [&](int s) {
        const u32 aoff = sb + s * STAGE_B + a_lm;
#pragma unroll
        for (int mf = 0; mf < 4; mf++) {
            LDSM4(ah[mf], aoff + mf * 768);
            LDSM4(al[mf], aoff + PLANE_B + mf * 768);
        }
    };
    auto COMPB = [&](int s) {
        const u32 boff = sb + s * STAGE_B + 2 * PLANE_B + b_lm;
#pragma unroll
        for (int g = 0; g < 4; g++) {
            u32 th[4], tl[4];
            LDSM4(th, boff + g * 768);
            LDSM4(tl, boff + PLANE_B + g * 768);
            u32 bh0[2] = { th[0], th[1] }, bh1[2] = { th[2], th[3] };
            u32 bl0[2] = { tl[0], tl[1] }, bl1[2] = { tl[2], tl[3] };
#pragma unroll
            for (int mf = 0; mf < 4; mf++) {
                MMA_BF16(c[mf][2 * g],     ah[mf], bh0);
                MMA_BF16(c[mf][2 * g],     ah[mf], bl0);
                MMA_BF16(c[mf][2 * g],     al[mf], bh0);
                MMA_BF16(c[mf][2 * g + 1], ah[mf], bh1);
                MMA_BF16(c[mf][2 * g + 1], ah[mf], bl1);
                MMA_BF16(c[mf][2 * g + 1], al[mf], bh1);
            }
        }
    };

    LOAD(0);
    STORE(0);
    LOAD(1);
    __syncthreads();
    LDA(0);

#pragma unroll 1
    for (int kt = 0; kt < 49; kt++) {
        const int s = kt & 1;
        if (kt < 48) {
            STORE(s ^ 1);
            if (kt < 47) LOAD(kt + 2);
        }
        COMPB(s);
        __syncthreads();
        if (kt < 48) LDA(s ^ 1);
    }

#pragma unroll
    for (int mf = 0; mf < 4; mf++) {
#pragma unroll
        for (int nf = 0; nf < 8; nf++) {
            const int row = bm + wm * 64 + mf * 16 + (lane >> 2);
            const int col = bn + wn * 64 + nf * 8 + (lane & 3) * 2;
            const float b0 = bias[col], b1 = bias[col + 1];
            float2 v0 = make_float2(c[mf][nf][0] + b0, c[mf][nf][1] + b1);
            float2 v1 = make_float2(c[mf][nf][2] + b0, c[mf][nf][3] + b1);
            *(float2*)(g_h + (size_t)row * 1024 + col) = v0;
            *(float2*)(g_h + (size_t)(row + 8) * 1024 + col) = v1;
        }
    }
}

// ---------------------------------------------------------------------------
// Kernel 2 (fused): RK4 Lorenz96 over [0,1] with h=1/16 (16 steps) + head.
// Block = 128 threads = one PAIR of batch rows; thread t owns 8 features.
// (round-11 proven version, unchanged)
// ---------------------------------------------------------------------------
__global__ void __launch_bounds__(128) rk4_head_kernel(
    const float* __restrict__ W2, const float* __restrict__ b2,
    float* __restrict__ out)
{
    const int t = threadIdx.x;
    const int warp = t >> 5;
    const float* p0 = g_h + (size_t)(2 * blockIdx.x) * 1024 + t * 8;
    const float* p1 = p0 + 1024;

    const float hf = 1.0f / 16.0f;
    const u64 NEG1 = pack2(-1.0f, -1.0f);
    const u64 F2   = pack2(8.0f, 8.0f);
    const u64 H05  = pack2(hf * 0.5f, hf * 0.5f);
    const u64 H1   = pack2(hf, hf);
    const u64 H6   = pack2(hf / 6.0f, hf / 6.0f);
    const u64 H3   = pack2(hf / 3.0f, hf / 3.0f);

    u64 x[8], y[8], xa[8];
#pragma unroll
    for (int j = 0; j < 2; j++) {
        float4 a = ((const float4*)p0)[j];
        float4 b = ((const float4*)p1)[j];
        x[4 * j + 0] = pack2(a.x, b.x);
        x[4 * j + 1] = pack2(a.y, b.y);
        x[4 * j + 2] = pack2(a.z, b.z);
        x[4 * j + 3] = pack2(a.w, b.w);
    }

    __shared__ u64 sA[2][128], sB[2][128], sC[2][128];
    __shared__ float2 red[4][10];
    __shared__ float2 lg[10];
    __shared__ float lse2[2];

    const int tl = (t + 127) & 127;
    const int tr = (t + 1) & 127;

    sA[0][t] = x[6]; sB[0][t] = x[7]; sC[0][t] = x[0];
    __syncthreads();
    int pb = 0;

#pragma unroll 1
    for (int s = 0; s < 16; s++) {
        {   // stage 1: k1 from x
            u64 ym2 = sA[pb][tl], ym1 = sB[pb][tl], hp1 = sC[pb][tr];
#pragma unroll
            for (int i = 0; i < 8; i++) {
                u64 vc = x[i];
                u64 vp = (i < 7) ? x[i + 1] : hp1;
                u64 k  = fma2(fma2(ym2, NEG1, vp), ym1, fma2(vc, NEG1, F2));
                xa[i]  = fma2(k, H6, x[i]);
                y[i]   = fma2(k, H05, x[i]);
                ym2 = ym1; ym1 = vc;
            }
            pb ^= 1;
            sA[pb][t] = y[6]; sB[pb][t] = y[7]; sC[pb][t] = y[0];
            __syncthreads();
        }
        {   // stage 2: k2 from y
            u64 ym2 = sA[pb][tl], ym1 = sB[pb][tl], hp1 = sC[pb][tr];
#pragma unroll
            for (int i = 0; i < 8; i++) {
                u64 vc = y[i];
                u64 vp = (i < 7) ? y[i + 1] : hp1;
                u64 k  = fma2(fma2(ym2, NEG1, vp), ym1, fma2(vc, NEG1, F2));
                xa[i]  = fma2(k, H3, xa[i]);
                y[i]   = fma2(k, H05, x[i]);
                ym2 = ym1; ym1 = vc;
            }
            pb ^= 1;
            sA[pb][t] = y[6]; sB[pb][t] = y[7]; sC[pb][t] = y[0];
            __syncthreads();
        }
        {   // stage 3: k3 from y
            u64 ym2 = sA[pb][tl], ym1 = sB[pb][tl], hp1 = sC[pb][tr];
#pragma unroll
            for (int i = 0; i < 8; i++) {
                u64 vc = y[i];
                u64 vp = (i < 7) ? y[i + 1] : hp1;
                u64 k  = fma2(fma2(ym2, NEG1, vp), ym1, fma2(vc, NEG1, F2));
                xa[i]  = fma2(k, H3, xa[i]);
                y[i]   = fma2(k, H1, x[i]);
                ym2 = ym1; ym1 = vc;
            }
            pb ^= 1;
            sA[pb][t] = y[6]; sB[pb][t] = y[7]; sC[pb][t] = y[0];
            __syncthreads();
        }
        {   // stage 4: k4 from y; x = xa + h/6 k4
            u64 ym2 = sA[pb][tl], ym1 = sB[pb][tl], hp1 = sC[pb][tr];
#pragma unroll
            for (int i = 0; i < 8; i++) {
                u64 vc = y[i];
                u64 vp = (i < 7) ? y[i + 1] : hp1;
                u64 k  = fma2(fma2(ym2, NEG1, vp), ym1, fma2(vc, NEG1, F2));
                x[i]   = fma2(k, H6, xa[i]);
                ym2 = ym1; ym1 = vc;
            }
            pb ^= 1;
            sA[pb][t] = x[6]; sB[pb][t] = x[7]; sC[pb][t] = x[0];
            __syncthreads();
        }
    }

    // ---- fused head: logits + log_softmax ----
    float lx[10], ly[10];
#pragma unroll
    for (int o = 0; o < 10; o++) {
        const float4* w4 = (const float4*)(W2 + (size_t)o * 1024 + t * 8);
        u64 a = 0ull;
#pragma unroll
        for (int j = 0; j < 2; j++) {
            float4 w = w4[j];
            a = fma2(x[4 * j + 0], pack2(w.x, w.x), a);
            a = fma2(x[4 * j + 1], pack2(w.y, w.y), a);
            a = fma2(x[4 * j + 2], pack2(w.z, w.z), a);
            a = fma2(x[4 * j + 3], pack2(w.w, w.w), a);
        }
        float2 v = unpack2(a);
#pragma unroll
        for (int off = 16; off > 0; off >>= 1) {
            v.x += __shfl_xor_sync(0xFFFFFFFFu, v.x, off);
            v.y += __shfl_xor_sync(0xFFFFFFFFu, v.y, off);
        }
        lx[o] = v.x; ly[o] = v.y;
    }
    if ((t & 31) == 0) {
#pragma unroll
        for (int o = 0; o < 10; o++) red[warp][o] = make_float2(lx[o], ly[o]);
    }
    __syncthreads();
    if (t < 10) {
        float gx = red[0][t].x + red[1][t].x + red[2][t].x + red[3][t].x + b2[t];
        float gy = red[0][t].y + red[1][t].y + red[2][t].y + red[3][t].y + b2[t];
        lg[t] = make_float2(gx, gy);
    }
    __syncthreads();
    if (t < 2) {
        float m = -1e30f;
#pragma unroll
        for (int o = 0; o < 10; o++) {
            float v = (t == 0) ? lg[o].x : lg[o].y;
            m = fmaxf(m, v);
        }
        float sum = 0.0f;
#pragma unroll
        for (int o = 0; o < 10; o++) {
            float v = (t == 0) ? lg[o].x : lg[o].y;
            sum += expf(v - m);
        }
        lse2[t] = logf(sum) + m;
    }
    __syncthreads();
    if (t < 10) {
        out[(size_t)(2 * blockIdx.x) * 10 + t]     = lg[t].x - lse2[0];
        out[(size_t)(2 * blockIdx.x + 1) * 10 + t] = lg[t].y - lse2[1];
    }
}

// ---------------------------------------------------------------------------
// Launch: serial full-width grids (overlap/cp.async/BK=32 all regressed;
// this is the consolidated best-of-each-component configuration).
// ---------------------------------------------------------------------------
extern "C" void kernel_launch(void* const* d_in, const int* in_sizes, int n_in,
                              void* d_out, int out_size)
{
    const float* x  = (const float*)d_in[0];  // [8192, 784]
    const float* W1 = (const float*)d_in[1];  // [1024, 784]
    const float* b1 = (const float*)d_in[2];  // [1024]
    const float* W2 = (const float*)d_in[3];  // [10, 1024]
    const float* b2 = (const float*)d_in[4];  // [10]
    float* out = (float*)d_out;               // [8192, 10]

    cudaFuncSetAttribute(gemm1_mma, cudaFuncAttributeMaxDynamicSharedMemorySize, GEMM_SMEM);

    // merged split: (8192 + 1024) rows x 196 tasks = 1,806,336 = 7056 * 256
    split_all_kernel<<<7056, 256>>>((const float4*)x, (const float4*)W1);

    dim3 g1(1024 / 128, 8192 / 128);          // (8, 64)
    gemm1_mma<<<g1, 128, GEMM_SMEM>>>(b1);
    rk4_head_kernel<<<8192 / 2, 128>>>(W2, b2, out);
}

// round 16
// speedup vs baseline: 1.2983x; 1.0478x over previous
#include <cuda_runtime.h>
#include <cstdint>

typedef unsigned long long u64;
typedef unsigned int u32;

// ===================== f32x2 helpers =====================
__device__ __forceinline__ u64 fma2(u64 a, u64 b, u64 c) {
    u64 d; asm("fma.rn.f32x2 %0, %1, %2, %3;" : "=l"(d) : "l"(a), "l"(b), "l"(c)); return d;
}
__device__ __forceinline__ u64 pack2(float lo, float hi) {
    u64 d; asm("mov.b64 %0, {%1, %2};" : "=l"(d) : "f"(lo), "f"(hi)); return d;
}
__device__ __forceinline__ float2 unpack2(u64 v) {
    float2 r; asm("mov.b64 {%0, %1}, %2;" : "=f"(r.x), "=f"(r.y) : "l"(v)); return r;
}

// Scratch: hidden state + pre-split bf16 planes (u32 = packed bf16x2),
// 392 u32 per row (784 fp32), no padding (BK=16 divides 784 exactly).
__device__ float g_h[8192 * 1024];
__device__ u32 g_xh[8192 * 392];
__device__ u32 g_xl[8192 * 392];
__device__ u32 g_wh[1024 * 392];
__device__ u32 g_wl[1024 * 392];

// ===================== mma.sync helpers =====================
__device__ __forceinline__ u32 smem_u32(const void* p) {
    u32 a;
    asm("{ .reg .u64 t; cvta.to.shared.u64 t, %1; cvt.u32.u64 %0, t; }" : "=r"(a) : "l"(p));
    return a;
}

#define LDSM4(r, addr) \
    asm volatile("ldmatrix.sync.aligned.m8n8.x4.shared.b16 {%0,%1,%2,%3}, [%4];" \
        : "=r"((r)[0]), "=r"((r)[1]), "=r"((r)[2]), "=r"((r)[3]) : "r"(addr))

#define MMA_BF16(c, a, b) \
    asm volatile("mma.sync.aligned.m16n8k16.row.col.f32.bf16.bf16.f32 " \
        "{%0,%1,%2,%3}, {%4,%5,%6,%7}, {%8,%9}, {%0,%1,%2,%3};" \
        : "+f"((c)[0]), "+f"((c)[1]), "+f"((c)[2]), "+f"((c)[3]) \
        : "r"((a)[0]), "r"((a)[1]), "r"((a)[2]), "r"((a)[3]), \
          "r"((b)[0]), "r"((b)[1]))

// split float pair -> bf16 hi-plane word + lo-plane word (lo16 = first elem)
__device__ __forceinline__ void split2(float x, float y, u32& hi, u32& lo) {
    u32 h;
    asm("cvt.rn.bf16x2.f32 %0, %1, %2;" : "=r"(h) : "f"(y), "f"(x));
    float hx = __uint_as_float(h << 16);
    float hy = __uint_as_float(h & 0xFFFF0000u);
    float lx = x - hx;
    float ly = y - hy;
    u32 l;
    asm("cvt.rn.bf16x2.f32 %0, %1, %2;" : "=r"(l) : "f"(ly), "f"(lx));
    hi = h; lo = l;
}

// ---------------------------------------------------------------------------
// Kernel 0 (merged): pre-split x AND W1 into bf16 hi/lo planes in one launch.
// 9216 rows x 196 float4 tasks = 1,806,336 = 7056 * 256 exactly.
// ---------------------------------------------------------------------------
__global__ void __launch_bounds__(256) split_all_kernel(
    const float4* __restrict__ x, const float4* __restrict__ w1)
{
    const int i = blockIdx.x * 256 + threadIdx.x;
    const int row = i / 196;
    const int j = i % 196;

    u32 *hi, *lo;
    const float4* src;
    int srow;
    if (row < 8192) { hi = g_xh; lo = g_xl; src = x;  srow = row; }
    else            { hi = g_wh; lo = g_wl; src = w1; srow = row - 8192; }

    float4 v = src[(size_t)srow * 196 + j];
    u32 h0, l0, h1, l1;
    split2(v.x, v.y, h0, l0);
    split2(v.z, v.w, h1, l1);
    const size_t dst = (size_t)srow * 392 + j * 2;
    *(uint2*)(hi + dst) = make_uint2(h0, h1);
    *(uint2*)(lo + dst) = make_uint2(l0, l1);
}

// smem geometry: BK=16 -> rows of 16 bf16 in 24-ushort (48B) stride.
static constexpr int ROW_US  = 24;
static constexpr int PLANE_B = 128 * ROW_US * 2;    // 6144 B per plane
static constexpr int STAGE_B = 4 * PLANE_B;         // Ah, Al, Bh, Bl = 24576
static constexpr int GEMM_SMEM = 2 * STAGE_B;       // 49152 dynamic

// ---------------------------------------------------------------------------
// Kernel 1: h = x @ W1^T + b1 from PRE-SPLIT bf16 planes. (round-11 proven)
// CTA 128x128, BK=16 (784 = 49*16), 4 warps (2x2), warp tile 64x64,
// double-buffered, 2 CTAs/SM, A-frag LDSM hoisted across the barrier.
// ---------------------------------------------------------------------------
__global__ void __launch_bounds__(128, 2) gemm1_mma(const float* __restrict__ bias)
{
    extern __shared__ __align__(16) char dsm[];
    const u32 sb = smem_u32(dsm);

    const int tid = threadIdx.x;
    const int wid = tid >> 5, lane = tid & 31;
    const int wm = wid >> 1;
    const int wn = wid & 1;
    const int bm = blockIdx.y * 128, bn = blockIdx.x * 128;

    const u32* Ahp = g_xh + (size_t)(bm + tid) * 392;
    const u32* Alp = g_xl + (size_t)(bm + tid) * 392;
    const u32* Bhp = g_wh + (size_t)(bn + tid) * 392;
    const u32* Blp = g_wl + (size_t)(bn + tid) * 392;

    uint4 vah[2], val[2], vbh[2], vbl[2];
    auto LOAD = [&](int kt) {
        const int k2 = kt * 8;
#pragma unroll
        for (int j = 0; j < 2; j++) {
            vah[j] = *(const uint4*)(Ahp + k2 + 4 * j);
            val[j] = *(const uint4*)(Alp + k2 + 4 * j);
            vbh[j] = *(const uint4*)(Bhp + k2 + 4 * j);
            vbl[j] = *(const uint4*)(Blp + k2 + 4 * j);
        }
    };
    auto STORE = [&](int s) {
        char* base = dsm + s * STAGE_B + tid * 48;
#pragma unroll
        for (int j = 0; j < 2; j++) {
            *(uint4*)(base + 16 * j)               = vah[j];
            *(uint4*)(base + PLANE_B + 16 * j)     = val[j];
            *(uint4*)(base + 2 * PLANE_B + 16 * j) = vbh[j];
            *(uint4*)(base + 3 * PLANE_B + 16 * j) = vbl[j];
        }
    };

    float c[4][8][4];
#pragma unroll
    for (int mf = 0; mf < 4; mf++)
#pragma unroll
        for (int nf = 0; nf < 8; nf++)
#pragma unroll
            for (int r = 0; r < 4; r++) c[mf][nf][r] = 0.0f;

    const u32 a_lm = (u32)((wm * 64 + (lane & 15)) * 48 + (lane >> 4) * 16);
    const u32 b_lm = (u32)((wn * 64 + ((lane & 16) >> 1) + (lane & 7)) * 48 + ((lane >> 3) & 1) * 16);

    u32 ah[4][4], al[4][4];          // A-frags, live across the barrier
    auto LDA = [&](int s) {
        const u32 aoff = sb + s * STAGE_B + a_lm;
#pragma unroll
        for (int mf = 0; mf < 4; mf++) {
            LDSM4(ah[mf], aoff + mf * 768);
            LDSM4(al[mf], aoff + PLANE_B + mf * 768);
        }
    };
    auto COMPB = [&](int s) {
        const u32 boff = sb + s * STAGE_B + 2 * PLANE_B + b_lm;
#pragma unroll
        for (int g = 0; g < 4; g++) {
            u32 th[4], tl[4];
            LDSM4(th, boff + g * 768);
            LDSM4(tl, boff + PLANE_B + g * 768);
            u32 bh0[2] = { th[0], th[1] }, bh1[2] = { th[2], th[3] };
            u32 bl0[2] = { tl[0], tl[1] }, bl1[2] = { tl[2], tl[3] };
#pragma unroll
            for (int mf = 0; mf < 4; mf++) {
                MMA_BF16(c[mf][2 * g],     ah[mf], bh0);
                MMA_BF16(c[mf][2 * g],     ah[mf], bl0);
                MMA_BF16(c[mf][2 * g],     al[mf], bh0);
                MMA_BF16(c[mf][2 * g + 1], ah[mf], bh1);
                MMA_BF16(c[mf][2 * g + 1], ah[mf], bl1);
                MMA_BF16(c[mf][2 * g + 1], al[mf], bh1);
            }
        }
    };

    LOAD(0);
    STORE(0);
    LOAD(1);
    __syncthreads();
    LDA(0);

#pragma unroll 1
    for (int kt = 0; kt < 49; kt++) {
        const int s = kt & 1;
        if (kt < 48) {
            STORE(s ^ 1);
            if (kt < 47) LOAD(kt + 2);
        }
        COMPB(s);
        __syncthreads();
        if (kt < 48) LDA(s ^ 1);
    }

#pragma unroll
    for (int mf = 0; mf < 4; mf++) {
#pragma unroll
        for (int nf = 0; nf < 8; nf++) {
            const int row = bm + wm * 64 + mf * 16 + (lane >> 2);
            const int col = bn + wn * 64 + nf * 8 + (lane & 3) * 2;
            const float b0 = bias[col], b1 = bias[col + 1];
            float2 v0 = make_float2(c[mf][nf][0] + b0, c[mf][nf][1] + b1);
            float2 v1 = make_float2(c[mf][nf][2] + b0, c[mf][nf][3] + b1);
            *(float2*)(g_h + (size_t)row * 1024 + col) = v0;
            *(float2*)(g_h + (size_t)(row + 8) * 1024 + col) = v1;
        }
    }
}

// ---------------------------------------------------------------------------
// Kernel 2 (fused): RK4 Lorenz96 over [0,1] with h=1/14 (14 steps) + head.
// Block = 128 threads = one PAIR of batch rows; thread t owns 8 features.
// (round-11 proven shape; only the step count / h changed)
// ---------------------------------------------------------------------------
__global__ void __launch_bounds__(128) rk4_head_kernel(
    const float* __restrict__ W2, const float* __restrict__ b2,
    float* __restrict__ out)
{
    const int t = threadIdx.x;
    const int warp = t >> 5;
    const float* p0 = g_h + (size_t)(2 * blockIdx.x) * 1024 + t * 8;
    const float* p1 = p0 + 1024;

    const float hf = 1.0f / 14.0f;
    const u64 NEG1 = pack2(-1.0f, -1.0f);
    const u64 F2   = pack2(8.0f, 8.0f);
    const u64 H05  = pack2(hf * 0.5f, hf * 0.5f);
    const u64 H1   = pack2(hf, hf);
    const u64 H6   = pack2(hf / 6.0f, hf / 6.0f);
    const u64 H3   = pack2(hf / 3.0f, hf / 3.0f);

    u64 x[8], y[8], xa[8];
#pragma unroll
    for (int j = 0; j < 2; j++) {
        float4 a = ((const float4*)p0)[j];
        float4 b = ((const float4*)p1)[j];
        x[4 * j + 0] = pack2(a.x, b.x);
        x[4 * j + 1] = pack2(a.y, b.y);
        x[4 * j + 2] = pack2(a.z, b.z);
        x[4 * j + 3] = pack2(a.w, b.w);
    }

    __shared__ u64 sA[2][128], sB[2][128], sC[2][128];
    __shared__ float2 red[4][10];
    __shared__ float2 lg[10];
    __shared__ float lse2[2];

    const int tl = (t + 127) & 127;
    const int tr = (t + 1) & 127;

    sA[0][t] = x[6]; sB[0][t] = x[7]; sC[0][t] = x[0];
    __syncthreads();
    int pb = 0;

#pragma unroll 1
    for (int s = 0; s < 14; s++) {
        {   // stage 1: k1 from x
            u64 ym2 = sA[pb][tl], ym1 = sB[pb][tl], hp1 = sC[pb][tr];
#pragma unroll
            for (int i = 0; i < 8; i++) {
                u64 vc = x[i];
                u64 vp = (i < 7) ? x[i + 1] : hp1;
                u64 k  = fma2(fma2(ym2, NEG1, vp), ym1, fma2(vc, NEG1, F2));
                xa[i]  = fma2(k, H6, x[i]);
                y[i]   = fma2(k, H05, x[i]);
                ym2 = ym1; ym1 = vc;
            }
            pb ^= 1;
            sA[pb][t] = y[6]; sB[pb][t] = y[7]; sC[pb][t] = y[0];
            __syncthreads();
        }
        {   // stage 2: k2 from y
            u64 ym2 = sA[pb][tl], ym1 = sB[pb][tl], hp1 = sC[pb][tr];
#pragma unroll
            for (int i = 0; i < 8; i++) {
                u64 vc = y[i];
                u64 vp = (i < 7) ? y[i + 1] : hp1;
                u64 k  = fma2(fma2(ym2, NEG1, vp), ym1, fma2(vc, NEG1, F2));
                xa[i]  = fma2(k, H3, xa[i]);
                y[i]   = fma2(k, H05, x[i]);
                ym2 = ym1; ym1 = vc;
            }
            pb ^= 1;
            sA[pb][t] = y[6]; sB[pb][t] = y[7]; sC[pb][t] = y[0];
            __syncthreads();
        }
        {   // stage 3: k3 from y
            u64 ym2 = sA[pb][tl], ym1 = sB[pb][tl], hp1 = sC[pb][tr];
#pragma unroll
            for (int i = 0; i < 8; i++) {
                u64 vc = y[i];
                u64 vp = (i < 7) ? y[i + 1] : hp1;
                u64 k  = fma2(fma2(ym2, NEG1, vp), ym1, fma2(vc, NEG1, F2));
                xa[i]  = fma2(k, H3, xa[i]);
                y[i]   = fma2(k, H1, x[i]);
                ym2 = ym1; ym1 = vc;
            }
            pb ^= 1;
            sA[pb][t] = y[6]; sB[pb][t] = y[7]; sC[pb][t] = y[0];
            __syncthreads();
        }
        {   // stage 4: k4 from y; x = xa + h/6 k4
            u64 ym2 = sA[pb][tl], ym1 = sB[pb][tl], hp1 = sC[pb][tr];
#pragma unroll
            for (int i = 0; i < 8; i++) {
                u64 vc = y[i];
                u64 vp = (i < 7) ? y[i + 1] : hp1;
                u64 k  = fma2(fma2(ym2, NEG1, vp), ym1, fma2(vc, NEG1, F2));
                x[i]   = fma2(k, H6, xa[i]);
                ym2 = ym1; ym1 = vc;
            }
            pb ^= 1;
            sA[pb][t] = x[6]; sB[pb][t] = x[7]; sC[pb][t] = x[0];
            __syncthreads();
        }
    }

    // ---- fused head: logits + log_softmax ----
    float lx[10], ly[10];
#pragma unroll
    for (int o = 0; o < 10; o++) {
        const float4* w4 = (const float4*)(W2 + (size_t)o * 1024 + t * 8);
        u64 a = 0ull;
#pragma unroll
        for (int j = 0; j < 2; j++) {
            float4 w = w4[j];
            a = fma2(x[4 * j + 0], pack2(w.x, w.x), a);
            a = fma2(x[4 * j + 1], pack2(w.y, w.y), a);
            a = fma2(x[4 * j + 2], pack2(w.z, w.z), a);
            a = fma2(x[4 * j + 3], pack2(w.w, w.w), a);
        }
        float2 v = unpack2(a);
#pragma unroll
        for (int off = 16; off > 0; off >>= 1) {
            v.x += __shfl_xor_sync(0xFFFFFFFFu, v.x, off);
            v.y += __shfl_xor_sync(0xFFFFFFFFu, v.y, off);
        }
        lx[o] = v.x; ly[o] = v.y;
    }
    if ((t & 31) == 0) {
#pragma unroll
        for (int o = 0; o < 10; o++) red[warp][o] = make_float2(lx[o], ly[o]);
    }
    __syncthreads();
    if (t < 10) {
        float gx = red[0][t].x + red[1][t].x + red[2][t].x + red[3][t].x + b2[t];
        float gy = red[0][t].y + red[1][t].y + red[2][t].y + red[3][t].y + b2[t];
        lg[t] = make_float2(gx, gy);
    }
    __syncthreads();
    if (t < 2) {
        float m = -1e30f;
#pragma unroll
        for (int o = 0; o < 10; o++) {
            float v = (t == 0) ? lg[o].x : lg[o].y;
            m = fmaxf(m, v);
        }
        float sum = 0.0f;
#pragma unroll
        for (int o = 0; o < 10; o++) {
            float v = (t == 0) ? lg[o].x : lg[o].y;
            sum += expf(v - m);
        }
        lse2[t] = logf(sum) + m;
    }
    __syncthreads();
    if (t < 10) {
        out[(size_t)(2 * blockIdx.x) * 10 + t]     = lg[t].x - lse2[0];
        out[(size_t)(2 * blockIdx.x + 1) * 10 + t] = lg[t].y - lse2[1];
    }
}

// ---------------------------------------------------------------------------
// Launch: serial full-width grids (consolidated best configuration).
// ---------------------------------------------------------------------------
extern "C" void kernel_launch(void* const* d_in, const int* in_sizes, int n_in,
                              void* d_out, int out_size)
{
    const float* x  = (const float*)d_in[0];  // [8192, 784]
    const float* W1 = (const float*)d_in[1];  // [1024, 784]
    const float* b1 = (const float*)d_in[2];  // [1024]
    const float* W2 = (const float*)d_in[3];  // [10, 1024]
    const float* b2 = (const float*)d_in[4];  // [10]
    float* out = (float*)d_out;               // [8192, 10]

    cudaFuncSetAttribute(gemm1_mma, cudaFuncAttributeMaxDynamicSharedMemorySize, GEMM_SMEM);

    // merged split: (8192 + 1024) rows x 196 tasks = 1,806,336 = 7056 * 256
    split_all_kernel<<<7056, 256>>>((const float4*)x, (const float4*)W1);

    dim3 g1(1024 / 128, 8192 / 128);          // (8, 64)
    gemm1_mma<<<g1, 128, GEMM_SMEM>>>(b1);
    rk4_head_kernel<<<8192 / 2, 128>>>(W2, b2, out);
}